// round 6
// baseline (speedup 1.0000x reference)
#include <cuda_runtime.h>

#define HOP 160
#define NFFT 512
#define NMEL 64
#define NFREQ 257
#define PREEMPH 0.97f
#define LOG_GUARD 5.9604644775390625e-8f   // 2^-24

#define MAXB 32
#define MAXT 1601
#define WPB 8                      // frames (warps) per block
#define SEG (HOP * (WPB - 1) + NFFT)   // 1632 staged samples per block
#define SCHUNK 8                   // stats partial chunks per batch row

// ---- device scratch (no allocations allowed) ----
__device__ int    g_lo[NMEL], g_hi[NMEL];
__device__ float  g_mean[MAXB * NMEL];
__device__ float  g_rstd[MAXB * NMEL];
__device__ double g_ps[MAXB * SCHUNK * NMEL];
__device__ double g_pss[MAXB * SCHUNK * NMEL];
__device__ __align__(16) float g_logmel[(size_t)MAXB * MAXT * NMEL];  // [b*T+t, m]

// ---------------------------------------------------------------------------
// in-place natural-order DFT-8 (input time order, output freq order)
// ---------------------------------------------------------------------------
__device__ __forceinline__ void dft8(float* zr, float* zi) {
    const float C = 0.70710678118654752f;
    float tr[4], ti[4], ur[4], ui[4];
    #pragma unroll
    for (int p = 0; p < 4; p++) {
        tr[p] = zr[p] + zr[p + 4];  ti[p] = zi[p] + zi[p + 4];
        ur[p] = zr[p] - zr[p + 4];  ui[p] = zi[p] - zi[p + 4];
    }
    { float a = ur[1], bq = ui[1]; ur[1] = C * (a + bq); ui[1] = C * (bq - a); }
    { float a = ur[2], bq = ui[2]; ur[2] = bq; ui[2] = -a; }
    { float a = ur[3], bq = ui[3]; ur[3] = C * (bq - a); ui[3] = -C * (a + bq); }
    float ar = tr[0] + tr[2], ai = ti[0] + ti[2];
    float br = tr[0] - tr[2], bi = ti[0] - ti[2];
    float cr = tr[1] + tr[3], ci = ti[1] + ti[3];
    float dr = ti[1] - ti[3], di = -(tr[1] - tr[3]);
    zr[0] = ar + cr; zi[0] = ai + ci;
    zr[4] = ar - cr; zi[4] = ai - ci;
    zr[2] = br + dr; zi[2] = bi + di;
    zr[6] = br - dr; zi[6] = bi - di;
    ar = ur[0] + ur[2]; ai = ui[0] + ui[2];
    br = ur[0] - ur[2]; bi = ui[0] - ui[2];
    cr = ur[1] + ur[3]; ci = ui[1] + ui[3];
    dr = ui[1] - ui[3]; di = -(ur[1] - ur[3]);
    zr[1] = ar + cr; zi[1] = ai + ci;
    zr[5] = ar - cr; zi[5] = ai - ci;
    zr[3] = br + dr; zi[3] = bi + di;
    zr[7] = br - dr; zi[7] = bi - di;
}

// ---------------------------------------------------------------------------
// init: mel filter support ranges (one block per mel row)
// ---------------------------------------------------------------------------
__global__ __launch_bounds__(256) void init_kernel(const float* __restrict__ fb) {
    __shared__ int slo[256], shi[256];
    int m = blockIdx.x;
    int tid = threadIdx.x;
    int lo = NFREQ, hi = 0;
    for (int f = tid; f < NFREQ; f += 256) {
        if (fb[m * NFREQ + f] != 0.0f) { if (f < lo) lo = f; if (f > hi) hi = f; }
    }
    slo[tid] = lo; shi[tid] = hi;
    __syncthreads();
    for (int s = 128; s > 0; s >>= 1) {
        if (tid < s) {
            if (slo[tid + s] < slo[tid]) slo[tid] = slo[tid + s];
            if (shi[tid + s] > shi[tid]) shi[tid] = shi[tid + s];
        }
        __syncthreads();
    }
    if (tid == 0) { g_lo[m] = slo[0]; g_hi[m] = shi[0]; }
}

// ---------------------------------------------------------------------------
// frame kernel: block = 8 consecutive frames of one batch row.
// ---------------------------------------------------------------------------
__global__ __launch_bounds__(32 * WPB) void frame_kernel(
    const float* __restrict__ x, const float* __restrict__ win,
    const float* __restrict__ fb, int L, int T, int nchunk)
{
    __shared__ float  sy[SEG];
    __shared__ float2 wsh[256];
    __shared__ float  sh_re[WPB][288];   // transpose buffer / freq buffer (padded)
    __shared__ float  sh_im[WPB][288];
    __shared__ float  sh_pow[WPB][264];

    const int tid = threadIdx.x;
    const int b = blockIdx.x / nchunk;
    const int chunk = blockIdx.x - b * nchunk;
    const int t0 = chunk * WPB;
    const float* xb = x + (size_t)b * L;
    const int base0 = t0 * HOP - (NFFT / 2);

    const float2* win2 = (const float2*)win;
    for (int i = tid; i < 256; i += 32 * WPB) wsh[i] = win2[i];

    // ---- stage input segment: y[n] = preemph(x)[reflect(n)] ----
    if (base0 >= 1 && base0 + SEG <= L) {
        #pragma unroll
        for (int r = 0; r < 7; r++) {
            int i = tid + r * 256;
            if (i < SEG) {
                int n = base0 + i;
                sy[i] = xb[n] - PREEMPH * xb[n - 1];
            }
        }
    } else {
        #pragma unroll
        for (int r = 0; r < 7; r++) {
            int i = tid + r * 256;
            if (i < SEG) {
                int n = base0 + i;
                int q = n < 0 ? -n : n;
                if (q >= L) q = 2 * (L - 1) - q;
                sy[i] = (q == 0) ? xb[0] : (xb[q] - PREEMPH * xb[q - 1]);
            }
        }
    }
    __syncthreads();

    const int wid = tid >> 5;
    const int lane = tid & 31;
    const int t = t0 + wid;
    if (t >= T) return;
    const int fid = b * T + t;

    // ---- pack from shared: z[k] = y(2k) + i*y(2k+1), windowed ----
    float zr[8], zi[8];
    const float2* sy2 = (const float2*)sy;
    const int sb = 80 * wid;
    #pragma unroll
    for (int p = 0; p < 8; p++) {
        int k = lane + 32 * p;
        float2 w2 = wsh[k];
        float2 v = sy2[sb + k];
        zr[p] = w2.x * v.x;
        zi[p] = w2.y * v.y;
    }

    // ---- per-lane DFT8 over p ----
    dft8(zr, zi);

    // ---- per-lane twiddle: A[k1] *= exp(-2*pi*i*lane*k1/256) via chain ----
    {
        float s1, c1;
        sincospif((float)lane / 128.0f, &s1, &c1);
        float w1r = c1, w1i = -s1;
        float wr = w1r, wi = w1i;
        #pragma unroll
        for (int k1 = 1; k1 < 8; k1++) {
            float nr = zr[k1] * wr - zi[k1] * wi;
            zi[k1]   = zr[k1] * wi + zi[k1] * wr;
            zr[k1]   = nr;
            float nwr = wr * w1r - wi * w1i;
            wi = wr * w1i + wi * w1r;
            wr = nwr;
        }
    }

    // ---- cross-lane stages h=16, 8 (unified branch-free butterfly) ----
    #pragma unroll
    for (int st = 0; st < 2; st++) {
        int h = 16 >> st;
        bool up = (lane & h) != 0;
        float sg = up ? -1.0f : 1.0f;
        int j = lane & (h - 1);
        float ss, cc;
        sincospif((float)j / (float)h, &ss, &cc);
        float wr = up ? cc : 1.0f;
        float wi = up ? -ss : 0.0f;
        #pragma unroll
        for (int k1 = 0; k1 < 8; k1++) {
            float pr = __shfl_xor_sync(0xFFFFFFFFu, zr[k1], h);
            float pi = __shfl_xor_sync(0xFFFFFFFFu, zi[k1], h);
            float dr = fmaf(sg, zr[k1], pr);
            float di = fmaf(sg, zi[k1], pi);
            zr[k1] = dr * wr - di * wi;
            zi[k1] = dr * wi + di * wr;
        }
    }

    // ---- remaining 3 stages == 32 independent plain 8-pt FFTs, one/lane ----
    // transpose through shared: store B[k1][lane] at k1*33+lane (conflict-free)
    #pragma unroll
    for (int k1 = 0; k1 < 8; k1++) {
        sh_re[wid][k1 * 33 + lane] = zr[k1];
        sh_im[wid][k1 * 33 + lane] = zi[k1];
    }
    __syncwarp();
    {
        int lbase = (lane >> 2) * 33 + (lane & 3) * 8;
        #pragma unroll
        for (int l3 = 0; l3 < 8; l3++) {
            zr[l3] = sh_re[wid][lbase + l3];
            zi[l3] = sh_im[wid][lbase + l3];
        }
    }
    __syncwarp();
    dft8(zr, zi);
    // value in reg w of lane (k1'=lane>>2, g=lane&3) is Z[k1' + 32w + 8*bitrev2(g)]
    {
        int k1p = lane >> 2;
        int g = lane & 3;
        int brg = ((g & 1) << 1) | (g >> 1);
        int f0 = k1p + 8 * brg;
        #pragma unroll
        for (int w = 0; w < 8; w++) {
            int freq = f0 + 32 * w;
            int a = freq + (freq >> 3);
            sh_re[wid][a] = zr[w];
            sh_im[wid][a] = zi[w];
        }
    }
    __syncwarp();

    // ---- paired real-FFT split + power spectrum ----
    {
        float bs, bc;
        sincospif((float)lane / 256.0f, &bs, &bc);
        float wr = bc, wi = -bs;                       // exp(-i*pi*f/256), f=lane
        const float STC = 0.92387953251128674f;        // cos(pi/8)
        const float STS = -0.38268343236508977f;       // -sin(pi/8)
        #pragma unroll
        for (int r = 0; r < 4; r++) {
            int f = lane + 32 * r;                     // 0..127
            int g = 256 - f;                           // 129..256
            float zfr = sh_re[wid][f + (f >> 3)], zfi = sh_im[wid][f + (f >> 3)];
            float zgr = sh_re[wid][g + (g >> 3)], zgi = sh_im[wid][g + (g >> 3)];
            float er = 0.5f * (zfr + zgr);
            float ei = 0.5f * (zfi - zgi);
            float orr = 0.5f * (zfi + zgi);
            float oi  = -0.5f * (zfr - zgr);
            float ur = wr * orr - wi * oi;
            float ui = wr * oi + wi * orr;
            float ar = er + ur, ai = ei + ui;
            float br = er - ur, bi = ei - ui;
            sh_pow[wid][f] = fmaf(ar, ar, ai * ai);
            sh_pow[wid][g] = fmaf(br, br, bi * bi);
            float nr = wr * STC - wi * STS;
            wi = wr * STS + wi * STC;
            wr = nr;
        }
        if (lane == 0) {
            float hr = sh_re[wid][144], hi = sh_im[wid][144];  // Z[128] (padded)
            sh_pow[wid][128] = fmaf(hr, hr, hi * hi);
        }
    }
    __syncwarp();

    // ---- sparse mel projection + log (width-balanced: lane, 63-lane) ----
    {
        float* pw = sh_pow[wid];
        float* outp = g_logmel + (size_t)fid * NMEL;
        #pragma unroll
        for (int mm = 0; mm < 2; mm++) {
            int m = mm ? (63 - lane) : lane;
            int lo = g_lo[m], hi = g_hi[m];
            float acc = 0.0f;
            const float* frow = fb + m * NFREQ;
            int f = lo;
            for (; f + 3 <= hi; f += 4) {
                acc = fmaf(__ldg(frow + f),     pw[f],     acc);
                acc = fmaf(__ldg(frow + f + 1), pw[f + 1], acc);
                acc = fmaf(__ldg(frow + f + 2), pw[f + 2], acc);
                acc = fmaf(__ldg(frow + f + 3), pw[f + 3], acc);
            }
            for (; f <= hi; f++) acc = fmaf(__ldg(frow + f), pw[f], acc);
            outp[m] = __logf(acc + LOG_GUARD);
        }
    }
}

// ---------------------------------------------------------------------------
// stats phase 1: per (b, chunk) partial sums over t-range
// ---------------------------------------------------------------------------
__global__ __launch_bounds__(256) void stats_part_kernel(
    const int* __restrict__ seq_len, int T)
{
    __shared__ double sh_s[256];
    __shared__ double sh_ss[256];
    int bc = blockIdx.x;
    int b = bc / SCHUNK;
    int c = bc - b * SCHUNK;
    int m = threadIdx.x & 63;
    int ph = threadIdx.x >> 6;      // 4 phases
    int flen = seq_len[b] / HOP + 1;
    int chunkT = (T + SCHUNK - 1) / SCHUNK;
    int tbeg = c * chunkT;
    int tend = tbeg + chunkT;
    if (tend > flen) tend = flen;

    float s = 0.0f, ss = 0.0f;
    for (int t = tbeg + ph; t < tend; t += 4) {
        float v = g_logmel[((size_t)(b * T + t)) * NMEL + m];
        s += v;
        ss = fmaf(v, v, ss);
    }
    sh_s[threadIdx.x] = (double)s;
    sh_ss[threadIdx.x] = (double)ss;
    __syncthreads();
    if (ph == 0) {
        double ds = 0.0, dss = 0.0;
        #pragma unroll
        for (int i = 0; i < 4; i++) {
            ds += sh_s[m + 64 * i];
            dss += sh_ss[m + 64 * i];
        }
        g_ps[bc * NMEL + m] = ds;
        g_pss[bc * NMEL + m] = dss;
    }
}

// ---------------------------------------------------------------------------
// stats phase 2: reduce partials -> mean / rstd
// ---------------------------------------------------------------------------
__global__ __launch_bounds__(64) void stats_reduce_kernel(
    const int* __restrict__ seq_len)
{
    int b = blockIdx.x;
    int m = threadIdx.x;
    int flen = seq_len[b] / HOP + 1;
    double ds = 0.0, dss = 0.0;
    #pragma unroll
    for (int c = 0; c < SCHUNK; c++) {
        ds += g_ps[(b * SCHUNK + c) * NMEL + m];
        dss += g_pss[(b * SCHUNK + c) * NMEL + m];
    }
    double n = (double)flen;
    double mean = ds / n;
    double var = (dss - ds * ds / n) / (n - 1.0);
    if (var < 0.0) var = 0.0;
    double std = sqrt(var) + 1e-5;
    g_mean[b * NMEL + m] = (float)mean;
    g_rstd[b * NMEL + m] = (float)(1.0 / std);
}

// ---------------------------------------------------------------------------
// normalize + transpose [b,t,m] -> [b,m,t] with float4 global accesses
// ---------------------------------------------------------------------------
__global__ __launch_bounds__(256) void out_kernel(
    const int* __restrict__ seq_len, float* __restrict__ out,
    int T, int TP, int extra)
{
    __shared__ float tile[64][65];
    __shared__ float mu[64];
    __shared__ float rs[64];

    int tid = threadIdx.x;
    int b = blockIdx.y;
    int t0 = blockIdx.x * 64;
    int flen = seq_len[b] / HOP + 1;

    if (tid < 64) {
        mu[tid] = g_mean[b * NMEL + tid];
        rs[tid] = g_rstd[b * NMEL + tid];
    }
    __syncthreads();

    // phase 1: float4 rows from g_logmel -> normalized tile columns
    #pragma unroll
    for (int r = 0; r < 4; r++) {
        int idx = r * 256 + tid;        // 0..1023
        int tl = idx >> 4;              // 0..63
        int m4 = idx & 15;
        int t = t0 + tl;
        float4 v = make_float4(0.f, 0.f, 0.f, 0.f);
        bool ok = (t < flen);
        if (ok) v = *(const float4*)&g_logmel[((size_t)(b * T + t)) * NMEL + 4 * m4];
        int m0 = 4 * m4;
        tile[m0 + 0][tl] = ok ? (v.x - mu[m0 + 0]) * rs[m0 + 0] : 0.0f;
        tile[m0 + 1][tl] = ok ? (v.y - mu[m0 + 1]) * rs[m0 + 1] : 0.0f;
        tile[m0 + 2][tl] = ok ? (v.z - mu[m0 + 2]) * rs[m0 + 2] : 0.0f;
        tile[m0 + 3][tl] = ok ? (v.w - mu[m0 + 3]) * rs[m0 + 3] : 0.0f;
    }
    __syncthreads();

    // phase 2: tile rows -> float4 stores to out[b][m][t]
    #pragma unroll
    for (int r = 0; r < 4; r++) {
        int idx = r * 256 + tid;
        int m = idx >> 4;               // 0..63
        int q = idx & 15;
        int t = t0 + 4 * q;
        if (t < TP) {
            float4 v;
            v.x = tile[m][4 * q + 0];
            v.y = tile[m][4 * q + 1];
            v.z = tile[m][4 * q + 2];
            v.w = tile[m][4 * q + 3];
            *(float4*)&out[((size_t)b * NMEL + m) * TP + t] = v;
        }
    }

    if (blockIdx.x == 0 && tid == 0 && b < extra) {
        size_t tail = (size_t)gridDim.y * NMEL * TP;
        out[tail + b] = (float)flen;
    }
}

// ---------------------------------------------------------------------------
extern "C" void kernel_launch(void* const* d_in, const int* in_sizes, int n_in,
                              void* d_out, int out_size)
{
    const float* x   = (const float*)d_in[0];
    const int*   seq = (const int*)d_in[1];
    const float* win = (const float*)d_in[2];
    const float* fb  = (const float*)d_in[3];
    float* out = (float*)d_out;

    int B = in_sizes[1];
    int L = in_sizes[0] / B;
    int T = L / HOP + 1;
    int TP = ((T + 15) / 16) * 16;

    init_kernel<<<NMEL, 256>>>(fb);

    int nchunk_f = (T + WPB - 1) / WPB;
    frame_kernel<<<B * nchunk_f, 32 * WPB>>>(x, win, fb, L, T, nchunk_f);

    stats_part_kernel<<<B * SCHUNK, 256>>>(seq, T);
    stats_reduce_kernel<<<B, 64>>>(seq);

    int nchunk = (TP + 63) / 64;
    long long extra = (long long)out_size - (long long)B * NMEL * TP;
    int ex = extra > 0 ? (int)(extra < B ? extra : B) : 0;
    out_kernel<<<dim3(nchunk, B), 256>>>(seq, out, T, TP, ex);
}